// round 15
// baseline (speedup 1.0000x reference)
#include <cuda_runtime.h>
#include <cuda_fp16.h>
#include <cstdint>

// Problem constants (fixed by the dataset)
#define NMAX 100000
#define EMAX 1600000
#define HID  64

// ---------------- device scratch (no allocations allowed) ----------------
__device__ int    g_cnt[NMAX];
__device__ float  g_dinv[NMAX];
__device__ int    g_rowptr[NMAX + 1];
__device__ int    g_woff[NMAX];
__device__ int    g_boff[512];
__device__ int    g_csr_src[EMAX + NMAX];
__device__ __half g_Hh[(size_t)NMAX * 128];   // interleaved: cols 0-63 branch a, 64-127 branch b
__device__ float  g_Xa[(size_t)NMAX * HID];
__device__ float  g_Xb[(size_t)NMAX * HID];
// packed bf16x2 hi/lo W fragments: [W1a hi|lo][W1b hi|lo][W2a hi|lo][W2b hi|lo]
// sizes (uints): W1a 256*64 each, W1b 128*64, W2a/W2b 32*64.
__device__ unsigned g_Wp[2 * (256 + 128 + 32 + 32) * 64];

// ---------------- bf16 split helpers ----------------
// hi = top-16-bit truncation of fp32 (exact bf16, RZ); lo = RN bf16 of residual.
__device__ __forceinline__ unsigned prmt_hipack(unsigned a, unsigned b) {
    unsigned r;
    asm("prmt.b32 %0, %1, %2, 0x7632;" : "=r"(r) : "r"(a), "r"(b));
    return r;
}
__device__ __forceinline__ unsigned bf16x2_rn(float lo_elem, float hi_elem) {
    unsigned r;
    asm("cvt.rn.bf16x2.f32 %0, %1, %2;" : "=r"(r) : "f"(hi_elem), "f"(lo_elem));
    return r;
}
__device__ __forceinline__ float trunc_bf16f(float x) {
    return __uint_as_float(__float_as_uint(x) & 0xFFFF0000u);
}

__device__ __forceinline__ void mma_bf16(float* d, const unsigned* a, const unsigned* b) {
    asm("mma.sync.aligned.m16n8k16.row.col.f32.bf16.bf16.f32 "
        "{%0,%1,%2,%3}, {%4,%5,%6,%7}, {%8,%9}, {%0,%1,%2,%3};"
        : "+f"(d[0]), "+f"(d[1]), "+f"(d[2]), "+f"(d[3])
        : "r"(a[0]), "r"(a[1]), "r"(a[2]), "r"(a[3]),
          "r"(b[0]), "r"(b[1]));
}

// ---------------- W pre-split: pack hi/lo bf16x2 in k-pair layout -------------
// Element (kp, col) of matrix -> { bf16(W[2kp][col]), bf16(W[2kp+1][col]) }.
__global__ void k_wprep(const float* __restrict__ W1a, const float* __restrict__ W1b,
                        const float* __restrict__ W2a, const float* __restrict__ W2b) {
    int i = blockIdx.x * blockDim.x + threadIdx.x;
    if (i >= 28672) return;
    const float* W; int j, hoff, loff;
    if (i < 16384)      { W = W1a; j = i;         hoff = 0;     loff = 16384; }
    else if (i < 24576) { W = W1b; j = i - 16384; hoff = 32768; loff = 40960; }
    else if (i < 26624) { W = W2a; j = i - 24576; hoff = 49152; loff = 51200; }
    else                { W = W2b; j = i - 26624; hoff = 53248; loff = 55296; }
    int kp = j >> 6, col = j & 63;
    float w0 = W[(size_t)(2 * kp)     * 64 + col];
    float w1 = W[(size_t)(2 * kp + 1) * 64 + col];
    g_Wp[hoff + j] = prmt_hipack(__float_as_uint(w0), __float_as_uint(w1));
    g_Wp[loff + j] = bf16x2_rn(w0 - trunc_bf16f(w0), w1 - trunc_bf16f(w1));
}

// ---------------- graph build ----------------
__global__ void k_init_cnt(int n) {
    int i = blockIdx.x * blockDim.x + threadIdx.x;
    if (i < n) g_cnt[i] = 1;   // self-loop
}

__global__ void k_count(const int* __restrict__ dst, int e) {
    int i = blockIdx.x * blockDim.x + threadIdx.x;
    if (i < e) atomicAdd(&g_cnt[dst[i]], 1);
}

// single block, 512 threads: per-256-chunk sums + exclusive scan of chunk sums
__global__ void k_sumscan(int n, int nblk) {
    __shared__ int sh[512];
    int t = threadIdx.x;
    int s = 0;
    int base = t * 256;
    if (base < n) {
        int end = min(base + 256, n);
        for (int i = base; i < end; i += 4) {
            int4 v = *reinterpret_cast<const int4*>(&g_cnt[i]);
            s += v.x + v.y + v.z + v.w;
        }
    }
    sh[t] = s;
    for (int off = 1; off < 512; off <<= 1) {
        __syncthreads();
        int x = (t >= off) ? sh[t - off] : 0;
        __syncthreads();
        sh[t] += x;
    }
    __syncthreads();
    if (t < nblk) g_boff[t] = sh[t] - s;   // exclusive
}

__global__ void k_scanwrite(int n) {
    __shared__ int sh[256];
    int t = threadIdx.x;
    int i = blockIdx.x * 256 + t;
    int v = (i < n) ? g_cnt[i] : 0;
    sh[t] = v;
    for (int off = 1; off < 256; off <<= 1) {
        __syncthreads();
        int x = (t >= off) ? sh[t - off] : 0;
        __syncthreads();
        sh[t] += x;
    }
    __syncthreads();
    int excl = sh[t] - v;
    if (i < n) {
        int rp = g_boff[blockIdx.x] + excl;
        g_rowptr[i] = rp;
        g_dinv[i] = rsqrtf((float)v);
        // self-loop edge first (deterministic slot)
        g_csr_src[rp] = i;
        g_woff[i] = rp + 1;
        if (i == n - 1) g_rowptr[n] = rp + v;
    }
}

__global__ void k_scatter(const int* __restrict__ src, const int* __restrict__ dst, int e) {
    int i = blockIdx.x * blockDim.x + threadIdx.x;
    if (i >= e) return;
    int d = dst[i];
    int pos = atomicAdd(&g_woff[d], 1);
    g_csr_src[pos] = src[i];
}

// ---------------- dual tensor-core GEMM ---------------------------------
// Two independent problems in one launch (blockIdx < nb0 -> problem 0).
// H[r, co:co+64] = fp16( dinv[r] * (A[r,:K] @ W[K,64]) ), row stride 128 halfs.
// bf16 hi/lo 3-split on mma.m16n8k16 (hi*hi + hi*lo + lo*hi), fp32 accumulate.
// A tiles double-buffered in smem (one sync/iter, next-tile LDG overlaps MMA);
// B fragments read directly from pre-split packed W in global (L1-resident).
__global__ void __launch_bounds__(256) k_gemm_dual(
        const float* __restrict__ A0,
        const unsigned* __restrict__ Wh0, const unsigned* __restrict__ Wl0,
        int K0, int co0, int nb0,
        const float* __restrict__ A1,
        const unsigned* __restrict__ Wh1, const unsigned* __restrict__ Wl1,
        int K1, int co1,
        __half* __restrict__ Ch, int n) {
    constexpr int BM = 128, BK = 16, AST = 12;  // stride in 32-bit words
    __shared__ unsigned Ah[2][BM][AST];
    __shared__ unsigned Al[2][BM][AST];

    const float* A; const unsigned* WhP; const unsigned* WlP; int K, m0, co;
    if (blockIdx.x < nb0) { A = A0; WhP = Wh0; WlP = Wl0; K = K0; co = co0; m0 = blockIdx.x * BM; }
    else                  { A = A1; WhP = Wh1; WlP = Wl1; K = K1; co = co1; m0 = (blockIdx.x - nb0) * BM; }

    int tid  = threadIdx.x;
    int warp = tid >> 5;
    int lane = tid & 31;
    int q = lane & 3;        // threadID_in_group
    int g = lane >> 2;       // groupID
    int rg = warp & 3;       // row-group: rows rg*32 .. rg*32+31
    int cg = warp >> 2;      // col-group: cols cg*32 .. cg*32+31
    int mrow = rg * 32;
    int ncol = cg * 32;

    float acc[2][4][4];
    #pragma unroll
    for (int mt = 0; mt < 2; ++mt)
        #pragma unroll
        for (int nt = 0; nt < 4; ++nt)
            #pragma unroll
            for (int j = 0; j < 4; ++j) acc[mt][nt][j] = 0.f;

    // A staging coords: 512 float4 per tile, 2 per thread
    int a_row = tid >> 2;                // 0..63 (+64 on second pass)
    int a_c4  = (tid & 3) * 4;           // k offset 0,4,8,12
    float4 va[2];

    auto ldgA = [&](int k0) {
        #pragma unroll
        for (int r = 0; r < 2; ++r) {
            int gr = m0 + a_row + r * 64;
            va[r] = make_float4(0.f, 0.f, 0.f, 0.f);
            if (gr < n) va[r] = *reinterpret_cast<const float4*>(&A[(size_t)gr * K + k0 + a_c4]);
        }
    };
    auto stsA = [&](int buf) {
        #pragma unroll
        for (int r = 0; r < 2; ++r) {
            int row = a_row + r * 64;
            float4 v = va[r];
            unsigned bx = __float_as_uint(v.x), by = __float_as_uint(v.y);
            unsigned bz = __float_as_uint(v.z), bw = __float_as_uint(v.w);
            Ah[buf][row][(a_c4 >> 1)    ] = prmt_hipack(bx, by);
            Ah[buf][row][(a_c4 >> 1) + 1] = prmt_hipack(bz, bw);
            Al[buf][row][(a_c4 >> 1)    ] = bf16x2_rn(v.x - trunc_bf16f(v.x), v.y - trunc_bf16f(v.y));
            Al[buf][row][(a_c4 >> 1) + 1] = bf16x2_rn(v.z - trunc_bf16f(v.z), v.w - trunc_bf16f(v.w));
        }
    };

    int iters = K / BK;
    ldgA(0);
    stsA(0);
    __syncthreads();

    for (int it = 0; it < iters; ++it) {
        int cur = it & 1;
        if (it + 1 < iters) ldgA((it + 1) * BK);   // overlap next-tile loads with MMA

        int kp0 = (it * BK) >> 1;                   // k-pair base for W fragments
        // --- A fragments from smem ---
        unsigned ah[2][4], al[2][4];
        #pragma unroll
        for (int mt = 0; mt < 2; ++mt) {
            int rbase = mrow + mt * 16;
            ah[mt][0] = Ah[cur][rbase + g    ][q    ];
            ah[mt][1] = Ah[cur][rbase + g + 8][q    ];
            ah[mt][2] = Ah[cur][rbase + g    ][q + 4];
            ah[mt][3] = Ah[cur][rbase + g + 8][q + 4];
            al[mt][0] = Al[cur][rbase + g    ][q    ];
            al[mt][1] = Al[cur][rbase + g + 8][q    ];
            al[mt][2] = Al[cur][rbase + g    ][q + 4];
            al[mt][3] = Al[cur][rbase + g + 8][q + 4];
        }
        // --- B fragments direct from packed global W + MMAs ---
        #pragma unroll
        for (int nt = 0; nt < 4; ++nt) {
            int col = ncol + nt * 8 + g;
            unsigned bh[2], bl[2];
            bh[0] = __ldg(&WhP[(kp0 + q    ) * 64 + col]);
            bh[1] = __ldg(&WhP[(kp0 + q + 4) * 64 + col]);
            bl[0] = __ldg(&WlP[(kp0 + q    ) * 64 + col]);
            bl[1] = __ldg(&WlP[(kp0 + q + 4) * 64 + col]);
            #pragma unroll
            for (int mt = 0; mt < 2; ++mt) {
                mma_bf16(acc[mt][nt], ah[mt], bh);
                mma_bf16(acc[mt][nt], ah[mt], bl);
                mma_bf16(acc[mt][nt], al[mt], bh);
            }
        }
        if (it + 1 < iters) stsA(cur ^ 1);
        __syncthreads();
    }

    // epilogue: scale rows by dinv, convert fp16, write half2 fragments
    #pragma unroll
    for (int mt = 0; mt < 2; ++mt) {
        int r0 = m0 + mrow + mt * 16 + g;
        int r1 = r0 + 8;
        float d0 = (r0 < n) ? g_dinv[r0] : 0.f;
        float d1 = (r1 < n) ? g_dinv[r1] : 0.f;
        #pragma unroll
        for (int nt = 0; nt < 4; ++nt) {
            int col = co + ncol + nt * 8 + q * 2;
            if (r0 < n)
                *reinterpret_cast<__half2*>(&Ch[(size_t)r0 * 128 + col]) =
                    __floats2half2_rn(acc[mt][nt][0] * d0, acc[mt][nt][1] * d0);
            if (r1 < n)
                *reinterpret_cast<__half2*>(&Ch[(size_t)r1 * 128 + col]) =
                    __floats2half2_rn(acc[mt][nt][2] * d1, acc[mt][nt][3] * d1);
        }
    }
}

// ---------------- agg helper: per-lane 4-col fp32 accumulation over edges -----
// H row = 128 fp16 = 256 B = 32 uint2; lane covers cols 4*lane..4*lane+3
// -> index = s*32 + lane (one LDG.64 per edge per lane, fully coalesced).
struct Acc4 { float v[4]; };
__device__ __forceinline__ void acc_edge(Acc4& a, const uint2* __restrict__ hp,
                                         int s, int lane) {
    uint2 u = hp[(size_t)s * 32 + lane];
    __half2 h0 = *reinterpret_cast<__half2*>(&u.x);
    __half2 h1 = *reinterpret_cast<__half2*>(&u.y);
    float2 f0 = __half22float2(h0);
    float2 f1 = __half22float2(h1);
    a.v[0] += f0.x; a.v[1] += f0.y; a.v[2] += f1.x; a.v[3] += f1.y;
}

// ---------------- agg1: both branches, bias+ELU, fp32 out (feeds gemm2) -------
__global__ void __launch_bounds__(256) k_agg1(
        const __half* __restrict__ H,
        const float* __restrict__ b0, const float* __restrict__ b1,
        float* __restrict__ Xa, float* __restrict__ Xb, int n) {
    int node = (blockIdx.x * blockDim.x + threadIdx.x) >> 5;
    int lane = threadIdx.x & 31;
    if (node >= n) return;
    const uint2* hp = reinterpret_cast<const uint2*>(H);
    int start = g_rowptr[node];
    int end   = g_rowptr[node + 1];
    Acc4 a; a.v[0] = a.v[1] = a.v[2] = a.v[3] = 0.f;
    int j = start;
    for (; j + 4 <= end; j += 4) {
        int s0 = g_csr_src[j];
        int s1 = g_csr_src[j + 1];
        int s2 = g_csr_src[j + 2];
        int s3 = g_csr_src[j + 3];
        acc_edge(a, hp, s0, lane);
        acc_edge(a, hp, s1, lane);
        acc_edge(a, hp, s2, lane);
        acc_edge(a, hp, s3, lane);
    }
    for (; j < end; ++j) acc_edge(a, hp, g_csr_src[j], lane);

    float dd = g_dinv[node];
    float4 bb = (lane < 16)
        ? reinterpret_cast<const float4*>(b0)[lane]
        : reinterpret_cast<const float4*>(b1)[lane - 16];
    float4 r;
    r.x = a.v[0] * dd + bb.x;
    r.y = a.v[1] * dd + bb.y;
    r.z = a.v[2] * dd + bb.z;
    r.w = a.v[3] * dd + bb.w;
    r.x = r.x > 0.f ? r.x : expm1f(r.x);
    r.y = r.y > 0.f ? r.y : expm1f(r.y);
    r.z = r.z > 0.f ? r.z : expm1f(r.z);
    r.w = r.w > 0.f ? r.w : expm1f(r.w);
    if (lane < 16)
        reinterpret_cast<float4*>(&Xa[(size_t)node * 64])[lane] = r;
    else
        reinterpret_cast<float4*>(&Xb[(size_t)node * 64])[lane - 16] = r;
}

// ---------------- agg2 + classifier: out[node,4] directly ---------------------
__global__ void __launch_bounds__(256) k_agg2_final(
        const __half* __restrict__ H,
        const float* __restrict__ b0, const float* __restrict__ b1,
        const float* __restrict__ Wfc, const float* __restrict__ bfc,
        float* __restrict__ out, int n) {
    __shared__ float4 ws[128];   // Wfc rows: 128 x 4
    for (int i = threadIdx.x; i < 128; i += 256)
        ws[i] = reinterpret_cast<const float4*>(Wfc)[i];
    __syncthreads();

    int node = (blockIdx.x * blockDim.x + threadIdx.x) >> 5;
    int lane = threadIdx.x & 31;
    if (node >= n) return;
    const uint2* hp = reinterpret_cast<const uint2*>(H);
    int start = g_rowptr[node];
    int end   = g_rowptr[node + 1];
    Acc4 a; a.v[0] = a.v[1] = a.v[2] = a.v[3] = 0.f;
    int j = start;
    for (; j + 4 <= end; j += 4) {
        int s0 = g_csr_src[j];
        int s1 = g_csr_src[j + 1];
        int s2 = g_csr_src[j + 2];
        int s3 = g_csr_src[j + 3];
        acc_edge(a, hp, s0, lane);
        acc_edge(a, hp, s1, lane);
        acc_edge(a, hp, s2, lane);
        acc_edge(a, hp, s3, lane);
    }
    for (; j < end; ++j) acc_edge(a, hp, g_csr_src[j], lane);

    float dd = g_dinv[node];
    float4 bb = (lane < 16)
        ? reinterpret_cast<const float4*>(b0)[lane]
        : reinterpret_cast<const float4*>(b1)[lane - 16];
    float x0 = a.v[0] * dd + bb.x;
    float x1 = a.v[1] * dd + bb.y;
    float x2 = a.v[2] * dd + bb.z;
    float x3 = a.v[3] * dd + bb.w;
    x0 = x0 > 0.f ? x0 : expm1f(x0);
    x1 = x1 > 0.f ? x1 : expm1f(x1);
    x2 = x2 > 0.f ? x2 : expm1f(x2);
    x3 = x3 > 0.f ? x3 : expm1f(x3);

    // classifier: feature index of x_k is 4*lane + k (concat layout matches)
    float4 w0 = ws[4 * lane + 0];
    float4 w1 = ws[4 * lane + 1];
    float4 w2 = ws[4 * lane + 2];
    float4 w3 = ws[4 * lane + 3];
    float4 p;
    p.x = x0 * w0.x + x1 * w1.x + x2 * w2.x + x3 * w3.x;
    p.y = x0 * w0.y + x1 * w1.y + x2 * w2.y + x3 * w3.y;
    p.z = x0 * w0.z + x1 * w1.z + x2 * w2.z + x3 * w3.z;
    p.w = x0 * w0.w + x1 * w1.w + x2 * w2.w + x3 * w3.w;
    #pragma unroll
    for (int off = 16; off; off >>= 1) {
        p.x += __shfl_xor_sync(0xffffffff, p.x, off);
        p.y += __shfl_xor_sync(0xffffffff, p.y, off);
        p.z += __shfl_xor_sync(0xffffffff, p.z, off);
        p.w += __shfl_xor_sync(0xffffffff, p.w, off);
    }
    if (lane == 0) {
        float4 bf = *reinterpret_cast<const float4*>(bfc);
        p.x += bf.x; p.y += bf.y; p.z += bf.z; p.w += bf.w;
        reinterpret_cast<float4*>(out)[node] = p;
    }
}

// ---------------- host launch ----------------
extern "C" void kernel_launch(void* const* d_in, const int* in_sizes, int n_in,
                              void* d_out, int out_size) {
    const float* x1  = (const float*)d_in[0];
    const float* x2  = (const float*)d_in[1];
    const int*   ei  = (const int*)d_in[2];
    const float* W1a = (const float*)d_in[3];
    const float* b1a = (const float*)d_in[4];
    const float* W2a = (const float*)d_in[5];
    const float* b2a = (const float*)d_in[6];
    const float* W1b = (const float*)d_in[7];
    const float* b1b = (const float*)d_in[8];
    const float* W2b = (const float*)d_in[9];
    const float* b2b = (const float*)d_in[10];
    const float* Wfc = (const float*)d_in[11];
    const float* bfc = (const float*)d_in[12];
    float* out = (float*)d_out;

    int n = in_sizes[0] / 512;   // 100000
    int e = in_sizes[2] / 2;     // 1600000
    const int* srcA = ei;
    const int* dstA = ei + e;

    __half* pH;
    float *pXa, *pXb;
    unsigned* pW;
    cudaGetSymbolAddress((void**)&pH,  g_Hh);
    cudaGetSymbolAddress((void**)&pXa, g_Xa);
    cudaGetSymbolAddress((void**)&pXb, g_Xb);
    cudaGetSymbolAddress((void**)&pW,  g_Wp);

    int nblk = (n + 255) / 256;

    // W pre-split (independent of graph)
    k_wprep<<<112, 256>>>(W1a, W1b, W2a, W2b);

    // graph build
    k_init_cnt<<<(n + 255) / 256, 256>>>(n);
    k_count<<<(e + 255) / 256, 256>>>(dstA, e);
    k_sumscan<<<1, 512>>>(n, nblk);
    k_scanwrite<<<nblk, 256>>>(n);
    k_scatter<<<(e + 255) / 256, 256>>>(srcA, dstA, e);

    int nb = (n + 127) / 128;                       // 782
    int node_grid = (n * 32 + 255) / 256;           // one warp per node

    // layer 1 (both branches fused; outputs interleaved fp16 [node][128])
    k_gemm_dual<<<2 * nb, 256>>>(x1, pW + 0,     pW + 16384, 512, 0, nb,
                                 x2, pW + 32768, pW + 40960, 256, 64, pH, n);
    k_agg1<<<node_grid, 256>>>(pH, b1a, b1b, pXa, pXb, n);

    // layer 2 (both branches fused)
    k_gemm_dual<<<2 * nb, 256>>>(pXa, pW + 49152, pW + 51200, 64, 0, nb,
                                 pXb, pW + 53248, pW + 55296, 64, 64, pH, n);
    k_agg2_final<<<node_grid, 256>>>(pH, b2a, b2b, Wfc, bfc, out, n);
}

// round 16
// speedup vs baseline: 1.2134x; 1.2134x over previous
#include <cuda_runtime.h>
#include <cuda_fp16.h>
#include <cstdint>

// Problem constants (fixed by the dataset)
#define NMAX 100000
#define EMAX 1600000
#define HID  64

// ---------------- device scratch (no allocations allowed) ----------------
__device__ int    g_cnt[NMAX];
__device__ float  g_dinv[NMAX];
__device__ int    g_rowptr[NMAX + 1];
__device__ int    g_woff[NMAX];
__device__ int    g_bsum[512];
__device__ int    g_boff[512];
__device__ int    g_csr_src[EMAX + NMAX];
__device__ __half g_Hh[(size_t)NMAX * 128];   // interleaved: cols 0-63 branch a, 64-127 branch b
__device__ float  g_Xa[(size_t)NMAX * HID];
__device__ float  g_Xb[(size_t)NMAX * HID];

// ---------------- bf16 split helpers ----------------
// hi = top-16-bit truncation of fp32 (exact bf16, RZ); lo = RN bf16 of residual.
__device__ __forceinline__ unsigned prmt_hipack(unsigned a, unsigned b) {
    unsigned r;
    asm("prmt.b32 %0, %1, %2, 0x7632;" : "=r"(r) : "r"(a), "r"(b));
    return r;
}
__device__ __forceinline__ unsigned bf16x2_rn(float lo_elem, float hi_elem) {
    unsigned r;
    asm("cvt.rn.bf16x2.f32 %0, %1, %2;" : "=r"(r) : "f"(hi_elem), "f"(lo_elem));
    return r;
}
__device__ __forceinline__ float trunc_bf16f(float x) {
    return __uint_as_float(__float_as_uint(x) & 0xFFFF0000u);
}

__device__ __forceinline__ void mma_bf16(float* d, const unsigned* a, const unsigned* b) {
    asm("mma.sync.aligned.m16n8k16.row.col.f32.bf16.bf16.f32 "
        "{%0,%1,%2,%3}, {%4,%5,%6,%7}, {%8,%9}, {%0,%1,%2,%3};"
        : "+f"(d[0]), "+f"(d[1]), "+f"(d[2]), "+f"(d[3])
        : "r"(a[0]), "r"(a[1]), "r"(a[2]), "r"(a[3]),
          "r"(b[0]), "r"(b[1]));
}

// ---------------- graph build ----------------
__global__ void k_init_cnt(int n) {
    int i = blockIdx.x * blockDim.x + threadIdx.x;
    if (i < n) g_cnt[i] = 1;   // self-loop
}

__global__ void k_count(const int* __restrict__ dst, int e) {
    int i = blockIdx.x * blockDim.x + threadIdx.x;
    if (i < e) atomicAdd(&g_cnt[dst[i]], 1);
}

__global__ void k_blocksum(int n) {
    __shared__ int sh[256];
    int i = blockIdx.x * 256 + threadIdx.x;
    sh[threadIdx.x] = (i < n) ? g_cnt[i] : 0;
    __syncthreads();
    for (int off = 128; off; off >>= 1) {
        if (threadIdx.x < off) sh[threadIdx.x] += sh[threadIdx.x + off];
        __syncthreads();
    }
    if (threadIdx.x == 0) g_bsum[blockIdx.x] = sh[0];
}

// single block, 512 threads: exclusive scan of block sums
__global__ void k_topscan(int nblk) {
    __shared__ int sh[512];
    int t = threadIdx.x;
    int v = (t < nblk) ? g_bsum[t] : 0;
    sh[t] = v;
    for (int off = 1; off < 512; off <<= 1) {
        __syncthreads();
        int x = (t >= off) ? sh[t - off] : 0;
        __syncthreads();
        sh[t] += x;
    }
    __syncthreads();
    if (t < nblk) g_boff[t] = sh[t] - v;   // exclusive
}

__global__ void k_scanwrite(int n) {
    __shared__ int sh[256];
    int t = threadIdx.x;
    int i = blockIdx.x * 256 + t;
    int v = (i < n) ? g_cnt[i] : 0;
    sh[t] = v;
    for (int off = 1; off < 256; off <<= 1) {
        __syncthreads();
        int x = (t >= off) ? sh[t - off] : 0;
        __syncthreads();
        sh[t] += x;
    }
    __syncthreads();
    int excl = sh[t] - v;
    if (i < n) {
        int rp = g_boff[blockIdx.x] + excl;
        g_rowptr[i] = rp;
        g_dinv[i] = rsqrtf((float)v);
        // self-loop edge first (deterministic slot)
        g_csr_src[rp] = i;
        g_woff[i] = rp + 1;
        if (i == n - 1) g_rowptr[n] = rp + v;
    }
}

// ---------------- dual tensor-core GEMM (+ optional fused scatter blocks) -----
// Blocks [0, nbTotal): GEMM. Blocks [nbTotal, ...): CSR scatter (layer-1 launch
// only) — scatter depends only on g_woff/dinv (scanwrite), gemm only on dinv,
// so they run concurrently and the ~25us scatter hides under gemm1.
//
// GEMM: two independent problems (blockIdx < nb0 -> problem 0).
// H[r, co:co+64] = fp16( dinv[r] * (A[r,:K] @ W[K,64]) ), row stride 128 halfs.
// bf16 hi/lo 3-split on mma.m16n8k16 (hi*hi + hi*lo + lo*hi), fp32 accumulate.
__global__ void __launch_bounds__(256) k_gemm_dual(
        const float* __restrict__ A0, const float* __restrict__ W0, int K0, int co0,
        int nb0,
        const float* __restrict__ A1, const float* __restrict__ W1, int K1, int co1,
        __half* __restrict__ Ch, int n,
        int nbTotal, const int* __restrict__ srcE, const int* __restrict__ dstE, int e) {
    constexpr int BM = 128, BK = 16, AST = 12, WST = 12;  // strides in 32-bit words
    __shared__ unsigned Ah[BM][AST];
    __shared__ unsigned Al[BM][AST];
    __shared__ unsigned Wh[64][WST];
    __shared__ unsigned Wl[64][WST];

    if ((int)blockIdx.x >= nbTotal) {
        // ---- scatter role ----
        int i = (blockIdx.x - nbTotal) * blockDim.x + threadIdx.x;
        if (i < e) {
            int d = dstE[i];
            int pos = atomicAdd(&g_woff[d], 1);
            g_csr_src[pos] = srcE[i];
        }
        return;
    }

    const float* A; const float* W; int K; int m0; int co;
    if ((int)blockIdx.x < nb0) { A = A0; W = W0; K = K0; co = co0; m0 = blockIdx.x * BM; }
    else                       { A = A1; W = W1; K = K1; co = co1; m0 = (blockIdx.x - nb0) * BM; }

    int tid  = threadIdx.x;
    int warp = tid >> 5;
    int lane = tid & 31;
    int q = lane & 3;        // threadID_in_group
    int g = lane >> 2;       // groupID
    int rg = warp & 3;       // row-group: rows rg*32 .. rg*32+31
    int cg = warp >> 2;      // col-group: cols cg*32 .. cg*32+31
    int mrow = rg * 32;
    int ncol = cg * 32;

    float acc[2][4][4];
    #pragma unroll
    for (int mt = 0; mt < 2; ++mt)
        #pragma unroll
        for (int nt = 0; nt < 4; ++nt)
            #pragma unroll
            for (int j = 0; j < 4; ++j) acc[mt][nt][j] = 0.f;

    // staging coords
    int a_row = tid >> 2;                // 0..63 (+64 on second pass)
    int a_c4  = (tid & 3) * 4;           // k offset 0,4,8,12
    int w_col = tid & 63;                // 0..63
    int w_kb  = (tid >> 6) * 4;          // 0,4,8,12

    for (int k0 = 0; k0 < K; k0 += BK) {
        // --- stage A tile: 128x16, hi via PRMT truncation, lo via RN bf16 ---
        #pragma unroll
        for (int r = 0; r < 2; ++r) {
            int row = a_row + r * 64;
            int gr  = m0 + row;
            float4 v = make_float4(0.f, 0.f, 0.f, 0.f);
            if (gr < n) v = *reinterpret_cast<const float4*>(&A[(size_t)gr * K + k0 + a_c4]);
            unsigned bx = __float_as_uint(v.x), by = __float_as_uint(v.y);
            unsigned bz = __float_as_uint(v.z), bw = __float_as_uint(v.w);
            Ah[row][(a_c4 >> 1)    ] = prmt_hipack(bx, by);
            Ah[row][(a_c4 >> 1) + 1] = prmt_hipack(bz, bw);
            Al[row][(a_c4 >> 1)    ] = bf16x2_rn(v.x - trunc_bf16f(v.x), v.y - trunc_bf16f(v.y));
            Al[row][(a_c4 >> 1) + 1] = bf16x2_rn(v.z - trunc_bf16f(v.z), v.w - trunc_bf16f(v.w));
        }
        // --- stage W tile: 16x64, each thread 4 consecutive k for one col ---
        {
            float w0 = W[(size_t)(k0 + w_kb + 0) * 64 + w_col];
            float w1 = W[(size_t)(k0 + w_kb + 1) * 64 + w_col];
            float w2 = W[(size_t)(k0 + w_kb + 2) * 64 + w_col];
            float w3 = W[(size_t)(k0 + w_kb + 3) * 64 + w_col];
            Wh[w_col][(w_kb >> 1)    ] = prmt_hipack(__float_as_uint(w0), __float_as_uint(w1));
            Wh[w_col][(w_kb >> 1) + 1] = prmt_hipack(__float_as_uint(w2), __float_as_uint(w3));
            Wl[w_col][(w_kb >> 1)    ] = bf16x2_rn(w0 - trunc_bf16f(w0), w1 - trunc_bf16f(w1));
            Wl[w_col][(w_kb >> 1) + 1] = bf16x2_rn(w2 - trunc_bf16f(w2), w3 - trunc_bf16f(w3));
        }
        __syncthreads();

        // --- fragment loads + MMAs (one 16-k step) ---
        unsigned ah[2][4], al[2][4];
        #pragma unroll
        for (int mt = 0; mt < 2; ++mt) {
            int rbase = mrow + mt * 16;
            ah[mt][0] = Ah[rbase + g    ][q    ];
            ah[mt][1] = Ah[rbase + g + 8][q    ];
            ah[mt][2] = Ah[rbase + g    ][q + 4];
            ah[mt][3] = Ah[rbase + g + 8][q + 4];
            al[mt][0] = Al[rbase + g    ][q    ];
            al[mt][1] = Al[rbase + g + 8][q    ];
            al[mt][2] = Al[rbase + g    ][q + 4];
            al[mt][3] = Al[rbase + g + 8][q + 4];
        }
        #pragma unroll
        for (int nt = 0; nt < 4; ++nt) {
            int col = ncol + nt * 8 + g;
            unsigned bh[2], bl[2];
            bh[0] = Wh[col][q];
            bh[1] = Wh[col][q + 4];
            bl[0] = Wl[col][q];
            bl[1] = Wl[col][q + 4];
            #pragma unroll
            for (int mt = 0; mt < 2; ++mt) {
                mma_bf16(acc[mt][nt], ah[mt], bh);
                mma_bf16(acc[mt][nt], ah[mt], bl);
                mma_bf16(acc[mt][nt], al[mt], bh);
            }
        }
        __syncthreads();
    }

    // epilogue: scale rows by dinv, convert fp16, write half2 fragments
    #pragma unroll
    for (int mt = 0; mt < 2; ++mt) {
        int r0 = m0 + mrow + mt * 16 + g;
        int r1 = r0 + 8;
        float d0 = (r0 < n) ? g_dinv[r0] : 0.f;
        float d1 = (r1 < n) ? g_dinv[r1] : 0.f;
        #pragma unroll
        for (int nt = 0; nt < 4; ++nt) {
            int col = co + ncol + nt * 8 + q * 2;
            if (r0 < n)
                *reinterpret_cast<__half2*>(&Ch[(size_t)r0 * 128 + col]) =
                    __floats2half2_rn(acc[mt][nt][0] * d0, acc[mt][nt][1] * d0);
            if (r1 < n)
                *reinterpret_cast<__half2*>(&Ch[(size_t)r1 * 128 + col]) =
                    __floats2half2_rn(acc[mt][nt][2] * d1, acc[mt][nt][3] * d1);
        }
    }
}

// ---------------- agg helper: per-lane 4-col fp32 accumulation over edges -----
// H row = 128 fp16 = 256 B = 32 uint2; lane covers cols 4*lane..4*lane+3
// -> index = s*32 + lane (one LDG.64 per edge per lane, fully coalesced).
struct Acc4 { float v[4]; };
__device__ __forceinline__ void acc_edge(Acc4& a, const uint2* __restrict__ hp,
                                         int s, int lane) {
    uint2 u = hp[(size_t)s * 32 + lane];
    __half2 h0 = *reinterpret_cast<__half2*>(&u.x);
    __half2 h1 = *reinterpret_cast<__half2*>(&u.y);
    float2 f0 = __half22float2(h0);
    float2 f1 = __half22float2(h1);
    a.v[0] += f0.x; a.v[1] += f0.y; a.v[2] += f1.x; a.v[3] += f1.y;
}

// ---------------- agg1: both branches, bias+ELU, fp32 out (feeds gemm2) -------
__global__ void __launch_bounds__(256) k_agg1(
        const __half* __restrict__ H,
        const float* __restrict__ b0, const float* __restrict__ b1,
        float* __restrict__ Xa, float* __restrict__ Xb, int n) {
    int node = (blockIdx.x * blockDim.x + threadIdx.x) >> 5;
    int lane = threadIdx.x & 31;
    if (node >= n) return;
    const uint2* hp = reinterpret_cast<const uint2*>(H);
    int start = g_rowptr[node];
    int end   = g_rowptr[node + 1];
    Acc4 a; a.v[0] = a.v[1] = a.v[2] = a.v[3] = 0.f;
    int j = start;
    for (; j + 4 <= end; j += 4) {
        int s0 = g_csr_src[j];
        int s1 = g_csr_src[j + 1];
        int s2 = g_csr_src[j + 2];
        int s3 = g_csr_src[j + 3];
        acc_edge(a, hp, s0, lane);
        acc_edge(a, hp, s1, lane);
        acc_edge(a, hp, s2, lane);
        acc_edge(a, hp, s3, lane);
    }
    for (; j < end; ++j) acc_edge(a, hp, g_csr_src[j], lane);

    float dd = g_dinv[node];
    float4 bb = (lane < 16)
        ? reinterpret_cast<const float4*>(b0)[lane]
        : reinterpret_cast<const float4*>(b1)[lane - 16];
    float4 r;
    r.x = a.v[0] * dd + bb.x;
    r.y = a.v[1] * dd + bb.y;
    r.z = a.v[2] * dd + bb.z;
    r.w = a.v[3] * dd + bb.w;
    r.x = r.x > 0.f ? r.x : expm1f(r.x);
    r.y = r.y > 0.f ? r.y : expm1f(r.y);
    r.z = r.z > 0.f ? r.z : expm1f(r.z);
    r.w = r.w > 0.f ? r.w : expm1f(r.w);
    if (lane < 16)
        reinterpret_cast<float4*>(&Xa[(size_t)node * 64])[lane] = r;
    else
        reinterpret_cast<float4*>(&Xb[(size_t)node * 64])[lane - 16] = r;
}

// ---------------- agg2 + classifier: out[node,4] directly ---------------------
__global__ void __launch_bounds__(256) k_agg2_final(
        const __half* __restrict__ H,
        const float* __restrict__ b0, const float* __restrict__ b1,
        const float* __restrict__ Wfc, const float* __restrict__ bfc,
        float* __restrict__ out, int n) {
    __shared__ float4 ws[128];   // Wfc rows: 128 x 4
    for (int i = threadIdx.x; i < 128; i += 256)
        ws[i] = reinterpret_cast<const float4*>(Wfc)[i];
    __syncthreads();

    int node = (blockIdx.x * blockDim.x + threadIdx.x) >> 5;
    int lane = threadIdx.x & 31;
    if (node >= n) return;
    const uint2* hp = reinterpret_cast<const uint2*>(H);
    int start = g_rowptr[node];
    int end   = g_rowptr[node + 1];
    Acc4 a; a.v[0] = a.v[1] = a.v[2] = a.v[3] = 0.f;
    int j = start;
    for (; j + 4 <= end; j += 4) {
        int s0 = g_csr_src[j];
        int s1 = g_csr_src[j + 1];
        int s2 = g_csr_src[j + 2];
        int s3 = g_csr_src[j + 3];
        acc_edge(a, hp, s0, lane);
        acc_edge(a, hp, s1, lane);
        acc_edge(a, hp, s2, lane);
        acc_edge(a, hp, s3, lane);
    }
    for (; j < end; ++j) acc_edge(a, hp, g_csr_src[j], lane);

    float dd = g_dinv[node];
    float4 bb = (lane < 16)
        ? reinterpret_cast<const float4*>(b0)[lane]
        : reinterpret_cast<const float4*>(b1)[lane - 16];
    float x0 = a.v[0] * dd + bb.x;
    float x1 = a.v[1] * dd + bb.y;
    float x2 = a.v[2] * dd + bb.z;
    float x3 = a.v[3] * dd + bb.w;
    x0 = x0 > 0.f ? x0 : expm1f(x0);
    x1 = x1 > 0.f ? x1 : expm1f(x1);
    x2 = x2 > 0.f ? x2 : expm1f(x2);
    x3 = x3 > 0.f ? x3 : expm1f(x3);

    // classifier: feature index of x_k is 4*lane + k (concat layout matches)
    float4 w0 = ws[4 * lane + 0];
    float4 w1 = ws[4 * lane + 1];
    float4 w2 = ws[4 * lane + 2];
    float4 w3 = ws[4 * lane + 3];
    float4 p;
    p.x = x0 * w0.x + x1 * w1.x + x2 * w2.x + x3 * w3.x;
    p.y = x0 * w0.y + x1 * w1.y + x2 * w2.y + x3 * w3.y;
    p.z = x0 * w0.z + x1 * w1.z + x2 * w2.z + x3 * w3.z;
    p.w = x0 * w0.w + x1 * w1.w + x2 * w2.w + x3 * w3.w;
    #pragma unroll
    for (int off = 16; off; off >>= 1) {
        p.x += __shfl_xor_sync(0xffffffff, p.x, off);
        p.y += __shfl_xor_sync(0xffffffff, p.y, off);
        p.z += __shfl_xor_sync(0xffffffff, p.z, off);
        p.w += __shfl_xor_sync(0xffffffff, p.w, off);
    }
    if (lane == 0) {
        float4 bf = *reinterpret_cast<const float4*>(bfc);
        p.x += bf.x; p.y += bf.y; p.z += bf.z; p.w += bf.w;
        reinterpret_cast<float4*>(out)[node] = p;
    }
}

// ---------------- host launch ----------------
extern "C" void kernel_launch(void* const* d_in, const int* in_sizes, int n_in,
                              void* d_out, int out_size) {
    const float* x1  = (const float*)d_in[0];
    const float* x2  = (const float*)d_in[1];
    const int*   ei  = (const int*)d_in[2];
    const float* W1a = (const float*)d_in[3];
    const float* b1a = (const float*)d_in[4];
    const float* W2a = (const float*)d_in[5];
    const float* b2a = (const float*)d_in[6];
    const float* W1b = (const float*)d_in[7];
    const float* b1b = (const float*)d_in[8];
    const float* W2b = (const float*)d_in[9];
    const float* b2b = (const float*)d_in[10];
    const float* Wfc = (const float*)d_in[11];
    const float* bfc = (const float*)d_in[12];
    float* out = (float*)d_out;

    int n = in_sizes[0] / 512;   // 100000
    int e = in_sizes[2] / 2;     // 1600000
    const int* srcA = ei;
    const int* dstA = ei + e;

    __half* pH;
    float *pXa, *pXb;
    cudaGetSymbolAddress((void**)&pH,  g_Hh);
    cudaGetSymbolAddress((void**)&pXa, g_Xa);
    cudaGetSymbolAddress((void**)&pXb, g_Xb);

    int nblk = (n + 255) / 256;

    // graph build prefix (everything scatter/gemm1 depend on)
    k_init_cnt<<<(n + 255) / 256, 256>>>(n);
    k_count<<<(e + 255) / 256, 256>>>(dstA, e);
    k_blocksum<<<nblk, 256>>>(n);
    k_topscan<<<1, 512>>>(nblk);
    k_scanwrite<<<nblk, 256>>>(n);

    int nb = (n + 127) / 128;                       // 782
    int node_grid = (n * 32 + 255) / 256;           // one warp per node
    int scat_blocks = (e + 255) / 256;              // 6250

    // layer 1 (both branches fused) + CSR scatter hidden in the same launch
    k_gemm_dual<<<2 * nb + scat_blocks, 256>>>(
        x1, W1a, 512, 0, nb, x2, W1b, 256, 64, pH, n,
        2 * nb, srcA, dstA, e);
    k_agg1<<<node_grid, 256>>>(pH, b1a, b1b, pXa, pXb, n);

    // layer 2 (both branches fused; no scatter blocks)
    k_gemm_dual<<<2 * nb, 256>>>(
        pXa, W2a, 64, 0, nb, pXb, W2b, 64, 64, pH, n,
        2 * nb, nullptr, nullptr, 0);
    k_agg2_final<<<node_grid, 256>>>(pH, b2a, b2b, Wfc, bfc, out, n);
}

// round 17
// speedup vs baseline: 1.2314x; 1.0149x over previous
#include <cuda_runtime.h>
#include <cuda_fp16.h>
#include <cstdint>

// Problem constants (fixed by the dataset)
#define NMAX 100000
#define EMAX 1600000
#define HID  64

// ---------------- device scratch (no allocations allowed) ----------------
__device__ int    g_cnt[NMAX];          // zeroed at end of each launch (scanwrite)
__device__ float  g_dinv[NMAX];
__device__ int    g_rowptr[NMAX + 1];
__device__ int    g_woff[NMAX];
__device__ int    g_bsum[512];
__device__ int    g_boff[512];
__device__ int    g_scan_done;          // completion counter; reset by last block
__device__ int    g_csr_src[EMAX + NMAX];
__device__ __half g_Hh[(size_t)NMAX * 128];   // interleaved: cols 0-63 branch a, 64-127 branch b
__device__ float  g_Xa[(size_t)NMAX * HID];
__device__ float  g_Xb[(size_t)NMAX * HID];

// ---------------- bf16 split helpers ----------------
// hi = top-16-bit truncation of fp32 (exact bf16, RZ); lo = RN bf16 of residual.
__device__ __forceinline__ unsigned prmt_hipack(unsigned a, unsigned b) {
    unsigned r;
    asm("prmt.b32 %0, %1, %2, 0x7632;" : "=r"(r) : "r"(a), "r"(b));
    return r;
}
__device__ __forceinline__ unsigned bf16x2_rn(float lo_elem, float hi_elem) {
    unsigned r;
    asm("cvt.rn.bf16x2.f32 %0, %1, %2;" : "=r"(r) : "f"(hi_elem), "f"(lo_elem));
    return r;
}
__device__ __forceinline__ float trunc_bf16f(float x) {
    return __uint_as_float(__float_as_uint(x) & 0xFFFF0000u);
}

__device__ __forceinline__ void mma_bf16(float* d, const unsigned* a, const unsigned* b) {
    asm("mma.sync.aligned.m16n8k16.row.col.f32.bf16.bf16.f32 "
        "{%0,%1,%2,%3}, {%4,%5,%6,%7}, {%8,%9}, {%0,%1,%2,%3};"
        : "+f"(d[0]), "+f"(d[1]), "+f"(d[2]), "+f"(d[3])
        : "r"(a[0]), "r"(a[1]), "r"(a[2]), "r"(a[3]),
          "r"(b[0]), "r"(b[1]));
}

__device__ __forceinline__ void ldsm4(unsigned* r, unsigned addr) {
    asm volatile("ldmatrix.sync.aligned.m8n8.x4.shared.b16 {%0,%1,%2,%3}, [%4];"
        : "=r"(r[0]), "=r"(r[1]), "=r"(r[2]), "=r"(r[3]) : "r"(addr));
}

// ---------------- graph build ----------------
__global__ void k_count(const int* __restrict__ dst, int e) {
    int i = blockIdx.x * blockDim.x + threadIdx.x;
    if (i < e) atomicAdd(&g_cnt[dst[i]], 1);
}

// blocksum + (last block) exclusive scan of block sums, fused via completion counter
__global__ void k_blocksum_scan(int n, int nblk) {
    __shared__ int sh[256];
    int t = threadIdx.x;
    int i = blockIdx.x * 256 + t;
    sh[t] = (i < n) ? g_cnt[i] + 1 : 0;   // +1 = self-loop
    __syncthreads();
    for (int off = 128; off; off >>= 1) {
        if (t < off) sh[t] += sh[t + off];
        __syncthreads();
    }
    if (t == 0) g_bsum[blockIdx.x] = sh[0];
    __threadfence();
    __syncthreads();
    __shared__ int lastblk;
    if (t == 0) lastblk = (atomicAdd(&g_scan_done, 1) == nblk - 1);
    __syncthreads();
    if (!lastblk) return;
    // last block: exclusive scan of g_bsum[0..nblk) -> g_boff
    __shared__ int s2[512];
    int v0 = (t < nblk) ? g_bsum[t] : 0;
    int v1 = (t + 256 < nblk) ? g_bsum[t + 256] : 0;
    s2[t] = v0;
    s2[t + 256] = v1;
    for (int off = 1; off < 512; off <<= 1) {
        __syncthreads();
        int x0 = (t >= off) ? s2[t - off] : 0;
        int x1 = (t + 256 >= off) ? s2[t + 256 - off] : 0;
        __syncthreads();
        s2[t] += x0;
        s2[t + 256] += x1;
    }
    __syncthreads();
    if (t < nblk) g_boff[t] = s2[t] - v0;
    if (t + 256 < nblk) g_boff[t + 256] = s2[t + 256] - v1;
    if (t == 0) g_scan_done = 0;   // reset for next graph replay
}

__global__ void k_scanwrite(int n) {
    __shared__ int sh[256];
    int t = threadIdx.x;
    int i = blockIdx.x * 256 + t;
    int v = (i < n) ? g_cnt[i] + 1 : 0;   // +1 = self-loop
    sh[t] = v;
    for (int off = 1; off < 256; off <<= 1) {
        __syncthreads();
        int x = (t >= off) ? sh[t - off] : 0;
        __syncthreads();
        sh[t] += x;
    }
    __syncthreads();
    int excl = sh[t] - v;
    if (i < n) {
        int rp = g_boff[blockIdx.x] + excl;
        g_rowptr[i] = rp;
        g_dinv[i] = rsqrtf((float)v);
        // self-loop edge first (deterministic slot)
        g_csr_src[rp] = i;
        g_woff[i] = rp + 1;
        g_cnt[i] = 0;                     // leave zeroed for next launch
        if (i == n - 1) g_rowptr[n] = rp + v;
    }
}

// ---------------- dual tensor-core GEMM (+ optional fused scatter blocks) -----
// Blocks [0, nbTotal): GEMM. Blocks [nbTotal, ...): CSR scatter (layer-1 launch
// only) — scatter depends only on g_woff/dinv (scanwrite), gemm only on dinv,
// so they run concurrently and the scatter hides under gemm1.
//
// GEMM: two independent problems (blockIdx < nb0 -> problem 0).
// H[r, co:co+64] = fp16( dinv[r] * (A[r,:K] @ W[K,64]) ), row stride 128 halfs.
// bf16 hi/lo 3-split on mma.m16n8k16 (hi*hi + hi*lo + lo*hi), fp32 accumulate.
// Fragment loads via ldmatrix.x4 (8 LDSM/warp/iter vs 32 scalar LDS); 12-word
// smem row stride keeps every 8-lane LDSM phase bank-conflict-free.
__global__ void __launch_bounds__(256) k_gemm_dual(
        const float* __restrict__ A0, const float* __restrict__ W0, int K0, int co0,
        int nb0,
        const float* __restrict__ A1, const float* __restrict__ W1, int K1, int co1,
        __half* __restrict__ Ch, int n,
        int nbTotal, const int* __restrict__ srcE, const int* __restrict__ dstE, int e) {
    constexpr int BM = 128, BK = 16, AST = 12, WST = 12;  // strides in 32-bit words
    __shared__ __align__(16) unsigned Ah[BM][AST];
    __shared__ __align__(16) unsigned Al[BM][AST];
    __shared__ __align__(16) unsigned Wh[64][WST];
    __shared__ __align__(16) unsigned Wl[64][WST];

    if ((int)blockIdx.x >= nbTotal) {
        // ---- scatter role ----
        int i = (blockIdx.x - nbTotal) * blockDim.x + threadIdx.x;
        if (i < e) {
            int d = dstE[i];
            int pos = atomicAdd(&g_woff[d], 1);
            g_csr_src[pos] = srcE[i];
        }
        return;
    }

    const float* A; const float* W; int K; int m0; int co;
    if ((int)blockIdx.x < nb0) { A = A0; W = W0; K = K0; co = co0; m0 = blockIdx.x * BM; }
    else                       { A = A1; W = W1; K = K1; co = co1; m0 = (blockIdx.x - nb0) * BM; }

    int tid  = threadIdx.x;
    int warp = tid >> 5;
    int lane = tid & 31;
    int q = lane & 3;        // threadID_in_group
    int g = lane >> 2;       // groupID
    int rg = warp & 3;       // row-group: rows rg*32 .. rg*32+31
    int cg = warp >> 2;      // col-group: cols cg*32 .. cg*32+31
    int mrow = rg * 32;
    int ncol = cg * 32;

    float acc[2][4][4];
    #pragma unroll
    for (int mt = 0; mt < 2; ++mt)
        #pragma unroll
        for (int nt = 0; nt < 4; ++nt)
            #pragma unroll
            for (int j = 0; j < 4; ++j) acc[mt][nt][j] = 0.f;

    // ldmatrix lane addresses (loop-invariant; bytes, 48 B row stride)
    int grp = lane >> 3, lrow = lane & 7;
    int a_row = ((grp & 1) << 3) + lrow;   // A: r0/r2 rows+0-7, r1/r3 rows+8-15
    int a_wrd = (grp >> 1) << 2;           //    r0/r1 words 0-3, r2/r3 words 4-7
    int b_row = ((grp >> 1) << 3) + lrow;  // B: r0/r1 nt0 (+0-7), r2/r3 nt1 (+8-15)
    int b_wrd = (grp & 1) << 2;            //    r0/r2 words 0-3, r1/r3 words 4-7
    unsigned baseAh = (unsigned)__cvta_generic_to_shared(Ah);
    unsigned baseAl = (unsigned)__cvta_generic_to_shared(Al);
    unsigned baseWh = (unsigned)__cvta_generic_to_shared(Wh);
    unsigned baseWl = (unsigned)__cvta_generic_to_shared(Wl);
    unsigned adrAh[2], adrAl[2], adrBh[2], adrBl[2];
    #pragma unroll
    for (int mt = 0; mt < 2; ++mt) {
        unsigned off = (unsigned)(mrow + mt * 16 + a_row) * (AST * 4) + a_wrd * 4;
        adrAh[mt] = baseAh + off;
        adrAl[mt] = baseAl + off;
    }
    #pragma unroll
    for (int p = 0; p < 2; ++p) {
        unsigned off = (unsigned)(ncol + p * 16 + b_row) * (WST * 4) + b_wrd * 4;
        adrBh[p] = baseWh + off;
        adrBl[p] = baseWl + off;
    }

    // staging coords
    int s_row = tid >> 2;                // 0..63 (+64 on second pass)
    int s_c4  = (tid & 3) * 4;           // k offset 0,4,8,12
    int w_col = tid & 63;                // 0..63
    int w_kb  = (tid >> 6) * 4;          // 0,4,8,12

    for (int k0 = 0; k0 < K; k0 += BK) {
        // --- stage A tile: 128x16, hi via PRMT truncation, lo via RN bf16 ---
        #pragma unroll
        for (int r = 0; r < 2; ++r) {
            int row = s_row + r * 64;
            int gr  = m0 + row;
            float4 v = make_float4(0.f, 0.f, 0.f, 0.f);
            if (gr < n) v = *reinterpret_cast<const float4*>(&A[(size_t)gr * K + k0 + s_c4]);
            unsigned bx = __float_as_uint(v.x), by = __float_as_uint(v.y);
            unsigned bz = __float_as_uint(v.z), bw = __float_as_uint(v.w);
            Ah[row][(s_c4 >> 1)    ] = prmt_hipack(bx, by);
            Ah[row][(s_c4 >> 1) + 1] = prmt_hipack(bz, bw);
            Al[row][(s_c4 >> 1)    ] = bf16x2_rn(v.x - trunc_bf16f(v.x), v.y - trunc_bf16f(v.y));
            Al[row][(s_c4 >> 1) + 1] = bf16x2_rn(v.z - trunc_bf16f(v.z), v.w - trunc_bf16f(v.w));
        }
        // --- stage W tile: 16x64, each thread 4 consecutive k for one col ---
        {
            float w0 = W[(size_t)(k0 + w_kb + 0) * 64 + w_col];
            float w1 = W[(size_t)(k0 + w_kb + 1) * 64 + w_col];
            float w2 = W[(size_t)(k0 + w_kb + 2) * 64 + w_col];
            float w3 = W[(size_t)(k0 + w_kb + 3) * 64 + w_col];
            Wh[w_col][(w_kb >> 1)    ] = prmt_hipack(__float_as_uint(w0), __float_as_uint(w1));
            Wh[w_col][(w_kb >> 1) + 1] = prmt_hipack(__float_as_uint(w2), __float_as_uint(w3));
            Wl[w_col][(w_kb >> 1)    ] = bf16x2_rn(w0 - trunc_bf16f(w0), w1 - trunc_bf16f(w1));
            Wl[w_col][(w_kb >> 1) + 1] = bf16x2_rn(w2 - trunc_bf16f(w2), w3 - trunc_bf16f(w3));
        }
        __syncthreads();

        // --- fragment loads via ldmatrix + MMAs (one 16-k step) ---
        unsigned ah[2][4], al[2][4], bfh[2][4], bfl[2][4];
        #pragma unroll
        for (int mt = 0; mt < 2; ++mt) {
            ldsm4(ah[mt], adrAh[mt]);
            ldsm4(al[mt], adrAl[mt]);
        }
        #pragma unroll
        for (int p = 0; p < 2; ++p) {
            ldsm4(bfh[p], adrBh[p]);
            ldsm4(bfl[p], adrBl[p]);
        }
        #pragma unroll
        for (int p = 0; p < 2; ++p) {
            #pragma unroll
            for (int sub = 0; sub < 2; ++sub) {
                int nt = p * 2 + sub;
                unsigned bh[2] = {bfh[p][sub * 2], bfh[p][sub * 2 + 1]};
                unsigned bl[2] = {bfl[p][sub * 2], bfl[p][sub * 2 + 1]};
                #pragma unroll
                for (int mt = 0; mt < 2; ++mt) {
                    mma_bf16(acc[mt][nt], ah[mt], bh);
                    mma_bf16(acc[mt][nt], ah[mt], bl);
                    mma_bf16(acc[mt][nt], al[mt], bh);
                }
            }
        }
        __syncthreads();
    }

    // epilogue: scale rows by dinv, convert fp16, write half2 fragments
    #pragma unroll
    for (int mt = 0; mt < 2; ++mt) {
        int r0 = m0 + mrow + mt * 16 + g;
        int r1 = r0 + 8;
        float d0 = (r0 < n) ? g_dinv[r0] : 0.f;
        float d1 = (r1 < n) ? g_dinv[r1] : 0.f;
        #pragma unroll
        for (int nt = 0; nt < 4; ++nt) {
            int col = co + ncol + nt * 8 + q * 2;
            if (r0 < n)
                *reinterpret_cast<__half2*>(&Ch[(size_t)r0 * 128 + col]) =
                    __floats2half2_rn(acc[mt][nt][0] * d0, acc[mt][nt][1] * d0);
            if (r1 < n)
                *reinterpret_cast<__half2*>(&Ch[(size_t)r1 * 128 + col]) =
                    __floats2half2_rn(acc[mt][nt][2] * d1, acc[mt][nt][3] * d1);
        }
    }
}

// ---------------- agg helper: per-lane 4-col fp32 accumulation over edges -----
// H row = 128 fp16 = 256 B = 32 uint2; lane covers cols 4*lane..4*lane+3
// -> index = s*32 + lane (one LDG.64 per edge per lane, fully coalesced).
struct Acc4 { float v[4]; };
__device__ __forceinline__ void acc_edge(Acc4& a, const uint2* __restrict__ hp,
                                         int s, int lane) {
    uint2 u = hp[(size_t)s * 32 + lane];
    __half2 h0 = *reinterpret_cast<__half2*>(&u.x);
    __half2 h1 = *reinterpret_cast<__half2*>(&u.y);
    float2 f0 = __half22float2(h0);
    float2 f1 = __half22float2(h1);
    a.v[0] += f0.x; a.v[1] += f0.y; a.v[2] += f1.x; a.v[3] += f1.y;
}

// ---------------- agg1: both branches, bias+ELU, fp32 out (feeds gemm2) -------
__global__ void __launch_bounds__(256) k_agg1(
        const __half* __restrict__ H,
        const float* __restrict__ b0, const float* __restrict__ b1,
        float* __restrict__ Xa, float* __restrict__ Xb, int n) {
    int node = (blockIdx.x * blockDim.x + threadIdx.x) >> 5;
    int lane = threadIdx.x & 31;
    if (node >= n) return;
    const uint2* hp = reinterpret_cast<const uint2*>(H);
    int start = g_rowptr[node];
    int end   = g_rowptr[node + 1];
    Acc4 a; a.v[0] = a.v[1] = a.v[2] = a.v[3] = 0.f;
    int j = start;
    for (; j + 4 <= end; j += 4) {
        int s0 = g_csr_src[j];
        int s1 = g_csr_src[j + 1];
        int s2 = g_csr_src[j + 2];
        int s3 = g_csr_src[j + 3];
        acc_edge(a, hp, s0, lane);
        acc_edge(a, hp, s1, lane);
        acc_edge(a, hp, s2, lane);
        acc_edge(a, hp, s3, lane);
    }
    for (; j < end; ++j) acc_edge(a, hp, g_csr_src[j], lane);

    float dd = g_dinv[node];
    float4 bb = (lane < 16)
        ? reinterpret_cast<const float4*>(b0)[lane]
        : reinterpret_cast<const float4*>(b1)[lane - 16];
    float4 r;
    r.x = a.v[0] * dd + bb.x;
    r.y = a.v[1] * dd + bb.y;
    r.z = a.v[2] * dd + bb.z;
    r.w = a.v[3] * dd + bb.w;
    r.x = r.x > 0.f ? r.x : expm1f(r.x);
    r.y = r.y > 0.f ? r.y : expm1f(r.y);
    r.z = r.z > 0.f ? r.z : expm1f(r.z);
    r.w = r.w > 0.f ? r.w : expm1f(r.w);
    if (lane < 16)
        reinterpret_cast<float4*>(&Xa[(size_t)node * 64])[lane] = r;
    else
        reinterpret_cast<float4*>(&Xb[(size_t)node * 64])[lane - 16] = r;
}

// ---------------- agg2 + classifier: out[node,4] directly ---------------------
__global__ void __launch_bounds__(256) k_agg2_final(
        const __half* __restrict__ H,
        const float* __restrict__ b0, const float* __restrict__ b1,
        const float* __restrict__ Wfc, const float* __restrict__ bfc,
        float* __restrict__ out, int n) {
    __shared__ float4 ws[128];   // Wfc rows: 128 x 4
    for (int i = threadIdx.x; i < 128; i += 256)
        ws[i] = reinterpret_cast<const float4*>(Wfc)[i];
    __syncthreads();

    int node = (blockIdx.x * blockDim.x + threadIdx.x) >> 5;
    int lane = threadIdx.x & 31;
    if (node >= n) return;
    const uint2* hp = reinterpret_cast<const uint2*>(H);
    int start = g_rowptr[node];
    int end   = g_rowptr[node + 1];
    Acc4 a; a.v[0] = a.v[1] = a.v[2] = a.v[3] = 0.f;
    int j = start;
    for (; j + 4 <= end; j += 4) {
        int s0 = g_csr_src[j];
        int s1 = g_csr_src[j + 1];
        int s2 = g_csr_src[j + 2];
        int s3 = g_csr_src[j + 3];
        acc_edge(a, hp, s0, lane);
        acc_edge(a, hp, s1, lane);
        acc_edge(a, hp, s2, lane);
        acc_edge(a, hp, s3, lane);
    }
    for (; j < end; ++j) acc_edge(a, hp, g_csr_src[j], lane);

    float dd = g_dinv[node];
    float4 bb = (lane < 16)
        ? reinterpret_cast<const float4*>(b0)[lane]
        : reinterpret_cast<const float4*>(b1)[lane - 16];
    float x0 = a.v[0] * dd + bb.x;
    float x1 = a.v[1] * dd + bb.y;
    float x2 = a.v[2] * dd + bb.z;
    float x3 = a.v[3] * dd + bb.w;
    x0 = x0 > 0.f ? x0 : expm1f(x0);
    x1 = x1 > 0.f ? x1 : expm1f(x1);
    x2 = x2 > 0.f ? x2 : expm1f(x2);
    x3 = x3 > 0.f ? x3 : expm1f(x3);

    // classifier: feature index of x_k is 4*lane + k (concat layout matches)
    float4 w0 = ws[4 * lane + 0];
    float4 w1 = ws[4 * lane + 1];
    float4 w2 = ws[4 * lane + 2];
    float4 w3 = ws[4 * lane + 3];
    float4 p;
    p.x = x0 * w0.x + x1 * w1.x + x2 * w2.x + x3 * w3.x;
    p.y = x0 * w0.y + x1 * w1.y + x2 * w2.y + x3 * w3.y;
    p.z = x0 * w0.z + x1 * w1.z + x2 * w2.z + x3 * w3.z;
    p.w = x0 * w0.w + x1 * w1.w + x2 * w2.w + x3 * w3.w;
    #pragma unroll
    for (int off = 16; off; off >>= 1) {
        p.x += __shfl_xor_sync(0xffffffff, p.x, off);
        p.y += __shfl_xor_sync(0xffffffff, p.y, off);
        p.z += __shfl_xor_sync(0xffffffff, p.z, off);
        p.w += __shfl_xor_sync(0xffffffff, p.w, off);
    }
    if (lane == 0) {
        float4 bf = *reinterpret_cast<const float4*>(bfc);
        p.x += bf.x; p.y += bf.y; p.z += bf.z; p.w += bf.w;
        reinterpret_cast<float4*>(out)[node] = p;
    }
}

// ---------------- host launch ----------------
extern "C" void kernel_launch(void* const* d_in, const int* in_sizes, int n_in,
                              void* d_out, int out_size) {
    const float* x1  = (const float*)d_in[0];
    const float* x2  = (const float*)d_in[1];
    const int*   ei  = (const int*)d_in[2];
    const float* W1a = (const float*)d_in[3];
    const float* b1a = (const float*)d_in[4];
    const float* W2a = (const float*)d_in[5];
    const float* b2a = (const float*)d_in[6];
    const float* W1b = (const float*)d_in[7];
    const float* b1b = (const float*)d_in[8];
    const float* W2b = (const float*)d_in[9];
    const float* b2b = (const float*)d_in[10];
    const float* Wfc = (const float*)d_in[11];
    const float* bfc = (const float*)d_in[12];
    float* out = (float*)d_out;

    int n = in_sizes[0] / 512;   // 100000
    int e = in_sizes[2] / 2;     // 1600000
    const int* srcA = ei;
    const int* dstA = ei + e;

    __half* pH;
    float *pXa, *pXb;
    cudaGetSymbolAddress((void**)&pH,  g_Hh);
    cudaGetSymbolAddress((void**)&pXa, g_Xa);
    cudaGetSymbolAddress((void**)&pXb, g_Xb);

    int nblk = (n + 255) / 256;

    // graph build prefix (g_cnt starts zeroed: static init on first call,
    // re-zeroed by k_scanwrite on every call -> deterministic under replay)
    k_count<<<(e + 255) / 256, 256>>>(dstA, e);
    k_blocksum_scan<<<nblk, 256>>>(n, nblk);
    k_scanwrite<<<nblk, 256>>>(n);

    int nb = (n + 127) / 128;                       // 782
    int node_grid = (n * 32 + 255) / 256;           // one warp per node
    int scat_blocks = (e + 255) / 256;              // 6250

    // layer 1 (both branches fused) + CSR scatter hidden in the same launch
    k_gemm_dual<<<2 * nb + scat_blocks, 256>>>(
        x1, W1a, 512, 0, nb, x2, W1b, 256, 64, pH, n,
        2 * nb, srcA, dstA, e);
    k_agg1<<<node_grid, 256>>>(pH, b1a, b1b, pXa, pXb, n);

    // layer 2 (both branches fused; no scatter blocks)
    k_gemm_dual<<<2 * nb, 256>>>(
        pXa, W2a, 64, 0, nb, pXb, W2b, 64, 64, pH, n,
        2 * nb, nullptr, nullptr, 0);
    k_agg2_final<<<node_grid, 256>>>(pH, b2a, b2b, Wfc, bfc, out, n);
}